// round 15
// baseline (speedup 1.0000x reference)
#include <cuda_runtime.h>
#include <cuda_bf16.h>
#include <cstdint>

// Problem constants (fixed by the reference setup_inputs)
constexpr int T_STEPS = 2048;
constexpr int BATCH   = 8192;
constexpr int CHUNK   = 32;                  // timesteps per pipeline stage
constexpr int NCHUNK  = T_STEPS / CHUNK;     // 64
constexpr int STAGES  = 3;                   // x staging ring depth
constexpr int EPB     = 64;                  // elements per block (2 per lane)
constexpr int TPB     = 96;                  // w0: hidden n0, w1: hidden n1, w2: output
constexpr int HALF    = CHUNK / 2;           // steps loaded per hidden warp per chunk

// Izhikevich params (regular spiking)
#define IZH_A   0.02f
#define IZH_B   0.2f
#define IZH_C   (-65.0f)
#define IZH_D   8.0f
#define IZH_VTH 30.0f

// ─── dynamic smem layout (bytes) ───
constexpr int XRING_B = STAGES * CHUNK * EPB * 16;        // 98304: [STAGES][CHUNK][EPB] float4
constexpr int ZBUF_B  = 2 * 2 * (CHUNK / 4) * EPB * 16;   // 32768: [2][2][CHUNK/4][EPB] float4
constexpr int SMEM_TOTAL = XRING_B + ZBUF_B;              // 131072

__device__ __forceinline__ void cp_async16(void* smem_dst, const void* gmem_src) {
    uint32_t s = (uint32_t)__cvta_generic_to_shared(smem_dst);
    asm volatile("cp.async.cg.shared.global [%0], [%1], 16;\n" :: "r"(s), "l"(gmem_src) : "memory");
}
__device__ __forceinline__ void cp_commit() {
    asm volatile("cp.async.commit_group;\n" ::: "memory");
}
__device__ __forceinline__ void cp_wait1() {
    asm volatile("cp.async.wait_group 1;\n" ::: "memory");
}

// The reference polynomial, FROZEN source expression (bit-exact vs reference).
__device__ __forceinline__ float izh_poly(float v, float u, float I) {
    return v + (0.04f * v * v + 5.0f * v + 140.0f - u + I);
}

// Branch-proof bit-select: (m & b) | (~m & a)  — one LOP3. m is 0 or ~0.
__device__ __forceinline__ float fbitsel(float a, float b, int m) {
    return __int_as_float((__float_as_int(b) & m) | (__float_as_int(a) & ~m));
}

// bits(30.0f) — integer-domain threshold compare (valid for these bounded,
// NaN-free dynamics; identical result to the float compare).
#define VTH_BITS 0x41F00000

// One speculative step on an independent chain. State carried by caller.
struct Chain { float vn, up; int m; };

__device__ __forceinline__ float izh_step(Chain& s, float I, float Cop, float KC) {
    const float uB = s.up + IZH_D;               // == fma(z=1, D, u')
    const float pA = izh_poly(s.vn, s.up, I);    // no-spike path (frozen)
    const float pB = Cop + ((KC - uB) + I);      // spike path (hoisted head)
    const float vnn  = fbitsel(pA, pB, s.m);
    const float usel = fbitsel(s.up, uB, s.m);
    s.up = usel + IZH_A * (IZH_B * vnn - usel);  // frozen order
    s.m  = -(int)(__float_as_int(vnn) >= VTH_BITS);
    s.vn = vnn;
    return __int_as_float(s.m & 0x3f800000);     // 1.0f or 0.0f
}

__global__ __launch_bounds__(TPB) void snn_izh_ilp2_kernel(
    const float4* __restrict__ xs,     // [T, B] float4 (F_IN = 4)
    const float*  __restrict__ W_in,   // [2,4]
    const float*  __restrict__ b_in,   // [2]
    const float*  __restrict__ W_out,  // [1,2]
    const float*  __restrict__ b_out,  // [1]
    float*        __restrict__ out)    // [T, B]
{
    extern __shared__ char smem[];
    float4* xring = (float4*)smem;                     // [STAGES][CHUNK][EPB]
    float4* zbuf  = (float4*)(smem + XRING_B);         // [2][2][CHUNK/4][EPB]

    const int wid  = threadIdx.x >> 5;
    const int lane = threadIdx.x & 31;
    const int col0 = lane;                  // element slot A within block
    const int col1 = lane + 32;             // element slot B within block
    const int eb   = blockIdx.x * EPB;      // block's element base

    // Opaque C: keeps the runtime op sequence fixed (no constant folding).
    float Cop = IZH_C;
    asm volatile("" : "+f"(Cop));
    const float KC = 0.04f * Cop * Cop + 5.0f * Cop + 140.0f;  // loop-invariant head

    if (wid < 2) {
        // ───── HIDDEN warp: neuron n for BOTH element columns; loads its half ─────
        const int n = wid;
        const float w0 = W_in[n * 4 + 0];
        const float w1 = W_in[n * 4 + 1];
        const float w2 = W_in[n * 4 + 2];
        const float w3 = W_in[n * 4 + 3];
        const float bi = b_in[n];

        const float4* xpA = xs + (eb + col0);  // stride BATCH between timesteps
        const float4* xpB = xs + (eb + col1);
        const int soff = n * HALF;             // this warp's half of every chunk

        // prologue: stage s holds chunk s; issue stages 0..1 (2 groups)
        #pragma unroll
        for (int s = 0; s < STAGES - 1; s++) {
            #pragma unroll
            for (int k = 0; k < HALF; k++) {
                cp_async16(&xring[(s * CHUNK + soff + k) * EPB + col0],
                           xpA + (size_t)(s * CHUNK + soff + k) * BATCH);
                cp_async16(&xring[(s * CHUNK + soff + k) * EPB + col1],
                           xpB + (size_t)(s * CHUNK + soff + k) * BATCH);
            }
            cp_commit();
        }

        Chain a = { IZH_C, IZH_B * IZH_C, 0 };   // chain for col0
        Chain b = { IZH_C, IZH_B * IZH_C, 0 };   // chain for col1

        #pragma unroll 1
        for (int c = 0; c <= NCHUNK; c++) {
            if (c < NCHUNK) cp_wait1();   // oldest in-flight group (stage c) complete
            __syncthreads();              // publish x stage c cross-warp; zbuf handoff
            if (c < NCHUNK) {
                // Issue stage c+2 FIRST so the loads overlap this chunk's compute.
                const int ls = c + STAGES - 1;
                if (ls < NCHUNK) {
                    const int lslot = ls % STAGES;
                    #pragma unroll
                    for (int k = 0; k < HALF; k++) {
                        cp_async16(&xring[(lslot * CHUNK + soff + k) * EPB + col0],
                                   xpA + (size_t)(ls * CHUNK + soff + k) * BATCH);
                        cp_async16(&xring[(lslot * CHUNK + soff + k) * EPB + col1],
                                   xpB + (size_t)(ls * CHUNK + soff + k) * BATCH);
                    }
                }
                cp_commit();   // empty group at the tail keeps FIFO count uniform

                const int slot = c % STAGES;
                const int cb   = c & 1;
                float4 zqA, zqB;
                #pragma unroll
                for (int k = 0; k < CHUNK; k++) {
                    const float4 xA = xring[(slot * CHUNK + k) * EPB + col0];
                    const float4 xB = xring[(slot * CHUNK + k) * EPB + col1];
                    // input linear (frozen order), two independent elements
                    const float hA = w0 * xA.x + w1 * xA.y + w2 * xA.z + w3 * xA.w + bi;
                    const float hB = w0 * xB.x + w1 * xB.y + w2 * xB.z + w3 * xB.w + bi;

                    const float zA = izh_step(a, hA, Cop, KC);
                    const float zB = izh_step(b, hB, Cop, KC);

                    // pack 4 steps per STS.128 per column
                    if      ((k & 3) == 0) { zqA.x = zA; zqB.x = zB; }
                    else if ((k & 3) == 1) { zqA.y = zA; zqB.y = zB; }
                    else if ((k & 3) == 2) { zqA.z = zA; zqB.z = zB; }
                    else {
                        zqA.w = zA; zqB.w = zB;
                        zbuf[((cb * 2 + n) * (CHUNK / 4) + (k >> 2)) * EPB + col0] = zqA;
                        zbuf[((cb * 2 + n) * (CHUNK / 4) + (k >> 2)) * EPB + col1] = zqB;
                    }
                }
            }
        }
    } else {
        // ───── OUTPUT warp: both element columns (lags one chunk) ─────
        const float wo0 = W_out[0], wo1 = W_out[1];
        const float bo  = b_out[0];

        Chain a = { IZH_C, IZH_B * IZH_C, 0 };
        Chain b = { IZH_C, IZH_B * IZH_C, 0 };
        float* opA = out + (eb + col0);
        float* opB = out + (eb + col1);

        #pragma unroll 1
        for (int c = 0; c <= NCHUNK; c++) {
            __syncthreads();
            if (c > 0) {
                const int cb    = (c - 1) & 1;
                const int tbase = (c - 1) * CHUNK;
                #pragma unroll
                for (int g = 0; g < CHUNK / 4; g++) {
                    const float4 z0qA = zbuf[((cb * 2 + 0) * (CHUNK / 4) + g) * EPB + col0];
                    const float4 z1qA = zbuf[((cb * 2 + 1) * (CHUNK / 4) + g) * EPB + col0];
                    const float4 z0qB = zbuf[((cb * 2 + 0) * (CHUNK / 4) + g) * EPB + col1];
                    const float4 z1qB = zbuf[((cb * 2 + 1) * (CHUNK / 4) + g) * EPB + col1];
                    #pragma unroll
                    for (int j = 0; j < 4; j++) {
                        const float z0A = (j == 0) ? z0qA.x : (j == 1) ? z0qA.y : (j == 2) ? z0qA.z : z0qA.w;
                        const float z1A = (j == 0) ? z1qA.x : (j == 1) ? z1qA.y : (j == 2) ? z1qA.z : z1qA.w;
                        const float z0B = (j == 0) ? z0qB.x : (j == 1) ? z0qB.y : (j == 2) ? z0qB.z : z0qB.w;
                        const float z1B = (j == 0) ? z1qB.x : (j == 1) ? z1qB.y : (j == 2) ? z1qB.z : z1qB.w;

                        // output linear (frozen order)
                        const float yA = z0A * wo0 + z1A * wo1 + bo;
                        const float yB = z0B * wo0 + z1B * wo1 + bo;

                        const float z2A = izh_step(a, yA, Cop, KC);
                        const float z2B = izh_step(b, yB, Cop, KC);

                        opA[(size_t)(tbase + g * 4 + j) * BATCH] = z2A;
                        opB[(size_t)(tbase + g * 4 + j) * BATCH] = z2B;
                    }
                }
            }
        }
    }
}

extern "C" void kernel_launch(void* const* d_in, const int* in_sizes, int n_in,
                              void* d_out, int out_size) {
    const float4* xs    = (const float4*)d_in[0];
    const float*  W_in  = (const float*)d_in[1];
    const float*  b_in  = (const float*)d_in[2];
    const float*  W_out = (const float*)d_in[3];
    const float*  b_out = (const float*)d_in[4];
    float* out = (float*)d_out;

    static bool attr_set = false;   // idempotent host-side attribute set (no allocation)
    if (!attr_set) {
        cudaFuncSetAttribute(snn_izh_ilp2_kernel,
                             cudaFuncAttributeMaxDynamicSharedMemorySize, SMEM_TOTAL);
        attr_set = true;
    }

    dim3 grid(BATCH / EPB);   // 128 blocks -> one block per SM, single wave
    dim3 block(TPB);          // 3 warps: hidden n0 / hidden n1 / output
    snn_izh_ilp2_kernel<<<grid, block, SMEM_TOTAL>>>(xs, W_in, b_in, W_out, b_out, out);
}

// round 16
// speedup vs baseline: 2.7075x; 2.7075x over previous
#include <cuda_runtime.h>
#include <cuda_bf16.h>
#include <cstdint>

// Problem constants (fixed by the reference setup_inputs)
constexpr int T_STEPS = 2048;
constexpr int BATCH   = 8192;
constexpr int CHUNK   = 32;                  // timesteps per pipeline stage (= bits per spike mask)
constexpr int NCHUNK  = T_STEPS / CHUNK;     // 64
constexpr int STAGES  = 3;                   // x staging ring depth
constexpr int EPB     = 32;                  // elements per block
constexpr int TPB     = 96;                  // w0: hidden n0+loads, w1: hidden n1+loads, w2: output
constexpr int HALF    = CHUNK / 2;           // steps loaded per hidden warp per chunk

// Izhikevich params (regular spiking)
#define IZH_A   0.02f
#define IZH_B   0.2f
#define IZH_C   (-65.0f)
#define IZH_D   8.0f
#define IZH_VTH 30.0f

__device__ __forceinline__ void cp_async16(void* smem_dst, const void* gmem_src) {
    uint32_t s = (uint32_t)__cvta_generic_to_shared(smem_dst);
    asm volatile("cp.async.cg.shared.global [%0], [%1], 16;\n" :: "r"(s), "l"(gmem_src) : "memory");
}
__device__ __forceinline__ void cp_commit() {
    asm volatile("cp.async.commit_group;\n" ::: "memory");
}
__device__ __forceinline__ void cp_wait1() {
    asm volatile("cp.async.wait_group 1;\n" ::: "memory");
}

// The reference polynomial, FROZEN source expression (bit-exact vs reference).
__device__ __forceinline__ float izh_poly(float v, float u, float I) {
    return v + (0.04f * v * v + 5.0f * v + 140.0f - u + I);
}

// Branch-proof bit-select: (m & b) | (~m & a)  — one LOP3. m is 0 or ~0.
__device__ __forceinline__ float fbitsel(float a, float b, int m) {
    return __int_as_float((__float_as_int(b) & m) | (__float_as_int(a) & ~m));
}

// bits(30.0f) — integer-domain threshold compare (valid for these bounded,
// NaN-free dynamics; identical result to the float compare).
#define VTH_BITS 0x41F00000

__global__ __launch_bounds__(TPB) void snn_izh_zmask_kernel(
    const float4* __restrict__ xs,     // [T, B] float4 (F_IN = 4)
    const float*  __restrict__ W_in,   // [2,4]
    const float*  __restrict__ b_in,   // [2]
    const float*  __restrict__ W_out,  // [1,2]
    const float*  __restrict__ b_out,  // [1]
    float*        __restrict__ out)    // [T, B]
{
    // x staging ring: 3 stages x 32 steps x 32 lanes x float4 = 48 KB
    __shared__ float4 xring[STAGES][CHUNK][EPB];
    // spike bitmasks: [buf][neuron][lane] — one uint32 carries 32 steps of spikes
    __shared__ uint32_t zmask[2][2][EPB];

    const int wid  = threadIdx.x >> 5;
    const int lane = threadIdx.x & 31;
    const int elem = blockIdx.x * EPB + lane;

    // Opaque C: keeps the runtime op sequence fixed (no constant folding).
    float Cop = IZH_C;
    asm volatile("" : "+f"(Cop));
    const float KC = 0.04f * Cop * Cop + 5.0f * Cop + 140.0f;  // loop-invariant head

    if (wid < 2) {
        // ───── HIDDEN warp: owns neuron n, loads half of each chunk ─────
        const int n = wid;
        const float w0 = W_in[n * 4 + 0];
        const float w1 = W_in[n * 4 + 1];
        const float w2 = W_in[n * 4 + 2];
        const float w3 = W_in[n * 4 + 3];
        const float bi = b_in[n];

        const float4* xp = xs + elem;          // stride BATCH between timesteps
        const int soff = n * HALF;             // this warp's half of every chunk

        // prologue: stage s holds chunk s; issue stages 0..1 (2 groups)
        #pragma unroll
        for (int s = 0; s < STAGES - 1; s++) {
            #pragma unroll
            for (int k = 0; k < HALF; k++)
                cp_async16(&xring[s][soff + k][lane],
                           xp + (size_t)(s * CHUNK + soff + k) * BATCH);
            cp_commit();
        }

        // speculative state: vn = pre-reset v of prev step, up = u' (pre +D),
        // m = all-ones mask iff prev step spiked
        float vn = IZH_C;
        float up = IZH_B * IZH_C;
        int   m  = 0;

        #pragma unroll 1
        for (int c = 0; c <= NCHUNK; c++) {
            if (c < NCHUNK) cp_wait1();   // oldest in-flight group (stage c) complete
            __syncthreads();              // publish x stage c cross-warp; zmask handoff
            if (c < NCHUNK) {
                // Issue stage c+2 FIRST so the loads overlap this chunk's compute.
                const int ls = c + STAGES - 1;
                if (ls < NCHUNK) {
                    const int lslot = ls % STAGES;
                    #pragma unroll
                    for (int k = 0; k < HALF; k++)
                        cp_async16(&xring[lslot][soff + k][lane],
                                   xp + (size_t)(ls * CHUNK + soff + k) * BATCH);
                }
                cp_commit();   // empty group at the tail keeps FIFO count uniform

                const int slot = c % STAGES;
                const int cb   = c & 1;
                uint32_t zb = 0;            // 32 steps of spikes as bits
                #pragma unroll
                for (int k = 0; k < CHUNK; k++) {
                    const float4 x = xring[slot][k][lane];
                    // input linear (frozen order)
                    const float h = w0 * x.x + w1 * x.y + w2 * x.z + w3 * x.w + bi;

                    // speculative Izhikevich step, branch-proof selection
                    const float uB = up + IZH_D;              // == fma(z=1, D, u')
                    const float pA = izh_poly(vn, up, h);     // no-spike path (frozen)
                    const float pB = Cop + ((KC - uB) + h);   // spike path (hoisted head)
                    const float vnn  = fbitsel(pA, pB, m);
                    const float usel = fbitsel(up, uB, m);
                    up = usel + IZH_A * (IZH_B * vnn - usel); // frozen order
                    m  = -(int)(__float_as_int(vnn) >= VTH_BITS);
                    vn = vnn;

                    zb |= ((uint32_t)m & (1u << k));          // one LOP3
                }
                zmask[cb][n][lane] = zb;    // single STS.32 per chunk
            }
        }
    } else {
        // ───── OUTPUT warp (lags one chunk) ─────
        const float wo0 = W_out[0], wo1 = W_out[1];
        const float bo  = b_out[0];

        // 4-entry y table: y(z0,z1) computed ONCE with the frozen expression on
        // runtime-opaque 0.0f/1.0f -> bit-identical to the per-step computation.
        float one = 1.0f, zer = 0.0f;
        asm volatile("" : "+f"(one), "+f"(zer));
        const float y00 = zer * wo0 + zer * wo1 + bo;
        const float y10 = one * wo0 + zer * wo1 + bo;
        const float y01 = zer * wo0 + one * wo1 + bo;
        const float y11 = one * wo0 + one * wo1 + bo;

        float vn = IZH_C;
        float up = IZH_B * IZH_C;
        int   m  = 0;
        float* op = out + elem;

        #pragma unroll 1
        for (int c = 0; c <= NCHUNK; c++) {
            __syncthreads();
            if (c > 0) {
                const int cb    = (c - 1) & 1;
                const int tbase = (c - 1) * CHUNK;
                const uint32_t zb0 = zmask[cb][0][lane];
                const uint32_t zb1 = zmask[cb][1][lane];
                #pragma unroll
                for (int k = 0; k < CHUNK; k++) {
                    // spike bits -> all-ones masks
                    const int m0 = -(int)((zb0 >> k) & 1u);
                    const int m1 = -(int)((zb1 >> k) & 1u);
                    // output linear via table select (3 LOP3, zero FP ops)
                    const float ya = fbitsel(y00, y10, m0);   // z1 = 0 row
                    const float yb = fbitsel(y01, y11, m0);   // z1 = 1 row
                    const float y  = fbitsel(ya, yb, m1);

                    const float uB = up + IZH_D;
                    const float pA = izh_poly(vn, up, y);
                    const float pB = Cop + ((KC - uB) + y);
                    const float vnn  = fbitsel(pA, pB, m);
                    const float usel = fbitsel(up, uB, m);
                    up = usel + IZH_A * (IZH_B * vnn - usel);
                    m  = -(int)(__float_as_int(vnn) >= VTH_BITS);
                    vn = vnn;
                    const float z2 = __int_as_float(m & 0x3f800000);

                    op[(size_t)(tbase + k) * BATCH] = z2;
                }
            }
        }
    }
}

extern "C" void kernel_launch(void* const* d_in, const int* in_sizes, int n_in,
                              void* d_out, int out_size) {
    const float4* xs    = (const float4*)d_in[0];
    const float*  W_in  = (const float*)d_in[1];
    const float*  b_in  = (const float*)d_in[2];
    const float*  W_out = (const float*)d_in[3];
    const float*  b_out = (const float*)d_in[4];
    float* out = (float*)d_out;

    dim3 grid(BATCH / EPB);   // 256 blocks
    dim3 block(TPB);          // 3 warps: hidden n0 / hidden n1 / output
    snn_izh_zmask_kernel<<<grid, block>>>(xs, W_in, b_in, W_out, b_out, out);
}